// round 15
// baseline (speedup 1.0000x reference)
#include <cuda_runtime.h>

#define NBLK 148
#define NTHR 512
#define GSZ (NBLK * NTHR)
#define GBLK 37  // blocks per sample group (148 = 4*37)

typedef unsigned long long ull;

// smem layout (floats)
#define SW_A 0         // 12800: phaseA weights
#define SW_B 12800     // 12800: phaseB weights
#define RED_OFF 25600  // 512: reduction scratch
#define SMEM_FLOATS 26112
#define SMEM_BYTES (SMEM_FLOATS * 4)

struct P {
  const float *x, *w1, *w2;
  const float *bn1g, *bn1b, *bn2g, *bn2b;
  const float *wc1, *bc1, *bn3g, *bn3b;
  const float *wc2, *bc2, *bn4g, *bn4b;
  const float *wc3, *bc3, *bn5g, *bn5b;
  const float *wf1, *bf1, *wf2, *bf2;
  float *out;
};

// ---- f32x2 packed helpers (sm_103a FFMA2 path) ----
__device__ __forceinline__ ull dup2(float v) {
  ull r;
  asm("mov.b64 %0, {%1, %1};" : "=l"(r) : "f"(v));
  return r;
}
__device__ __forceinline__ void unpack2(ull p, float &lo, float &hi) {
  asm("mov.b64 {%0, %1}, %2;" : "=f"(lo), "=f"(hi) : "l"(p));
}
__device__ __forceinline__ ull ffma2(ull a, ull b, ull c) {
  ull d;
  asm("fma.rn.f32x2 %0, %1, %2, %3;" : "=l"(d) : "l"(a), "l"(b), "l"(c));
  return d;
}

// ---- persistent-kernel scratch (device globals; no allocation) ----
__device__ unsigned int g_cnt = 0;
__device__ volatile unsigned int g_gen = 0;
__device__ unsigned int g_cnt4[4] = {0, 0, 0, 0};
__device__ volatile unsigned int g_gen4[4] = {0, 0, 0, 0};

__device__ float g_xs[131072];
__device__ float g_drive[131072];
__device__ float g_a[204800];      // PADDED code a: [n][F][40][40], zero border
__device__ float g_recon[165888];  // LCA2: [n][16c][1296][2p]; LCA1: [n][3c][1296][4p]
__device__ float g_h[131072];
__device__ float g_m[256];
__device__ float g_rs[256];
__device__ float g_fc[2048];
__device__ float g_fcp[16384];

// chunk over the FULL grid
#define CHUNK_LOOP(NJOB)                                                   \
  const int _ck = ((NJOB) + NBLK - 1) / NBLK;                              \
  const int _j0 = blockIdx.x * _ck;                                        \
  const int _j1 = (_j0 + _ck < (NJOB)) ? (_j0 + _ck) : (NJOB);             \
  for (int idx = _j0 + (int)threadIdx.x; idx < _j1; idx += NTHR)

// chunk over one 37-block group (rank = position within group)
#define GCHUNK_LOOP(NJOB, RANK)                                            \
  const int _ck = ((NJOB) + GBLK - 1) / GBLK;                              \
  const int _j0 = (RANK) * _ck;                                            \
  const int _j1 = (_j0 + _ck < (NJOB)) ? (_j0 + _ck) : (NJOB);             \
  for (int idx = _j0 + (int)threadIdx.x; idx < _j1; idx += NTHR)

// ---- software grid barrier (all 148 blocks) ----
__device__ __forceinline__ void grid_sync() {
  __syncthreads();
  if (threadIdx.x == 0) {
    unsigned int gen = g_gen;
    __threadfence();  // release
    if (atomicAdd(&g_cnt, 1u) == (unsigned)(NBLK - 1)) {
      g_cnt = 0u;
      __threadfence();
      g_gen = gen + 1u;
    } else {
      while (g_gen == gen) {}
      __threadfence();  // acquire (CCTL.IVALL -> drop stale L1)
    }
  }
  __syncthreads();
}

// ---- per-sample group barrier (37 blocks) ----
__device__ __forceinline__ void group_sync(int grp) {
  __syncthreads();
  if (threadIdx.x == 0) {
    unsigned int gen = g_gen4[grp];
    __threadfence();  // release
    if (atomicAdd(&g_cnt4[grp], 1u) == (unsigned)(GBLK - 1)) {
      g_cnt4[grp] = 0u;
      __threadfence();
      g_gen4[grp] = gen + 1u;
    } else {
      while (g_gen4[grp] == gen) {}
      __threadfence();  // acquire
    }
  }
  __syncthreads();
}

__device__ __forceinline__ float block_reduce(float v, float *red) {
  red[threadIdx.x] = v;
  __syncthreads();
#pragma unroll
  for (int s = NTHR / 2; s > 0; s >>= 1) {
    if (threadIdx.x < s) red[threadIdx.x] += red[threadIdx.x + s];
    __syncthreads();
  }
  float r = red[0];
  __syncthreads();
  return r;
}

__device__ void zero_buf(float *b, int n) {
  for (int i = blockIdx.x * NTHR + threadIdx.x; i < n; i += GSZ) b[i] = 0.f;
}

__device__ void sample_stats(const float *in, int len, float *red) {
  for (int n = blockIdx.x; n < 4; n += NBLK) {
    const float *p = in + n * len;
    float s = 0.f, ss = 0.f;
    for (int i = threadIdx.x; i < len; i += NTHR) {
      float v = p[i];
      s += v;
      ss += v * v;
    }
    s = block_reduce(s, red);
    ss = block_reduce(ss, red);
    if (threadIdx.x == 0) {
      float m = s / (float)len;
      float var = fmaxf(ss / (float)len - m * m, 0.f);
      g_m[n] = m;
      g_rs[n] = 1.f / (sqrtf(var) + 1e-8f);
    }
    __syncthreads();
  }
}

__device__ void standardize(const float *in, float *out, int len) {
  for (int i = blockIdx.x * NTHR + threadIdx.x; i < 4 * len; i += GSZ) {
    int n = i / len;
    out[i] = (in[i] - g_m[n]) * g_rs[n];
  }
}

__device__ void conv5x5(const float *__restrict__ in, const float *__restrict__ w,
                        const float *__restrict__ bias, float *__restrict__ out,
                        int Cin, int Cout, int HW, bool do_relu) {
  int npix = HW * HW;
  const int NJOB = 4 * Cout * npix;
  CHUNK_LOOP(NJOB) {
    int x = idx % HW;
    int t = idx / HW;
    int y = t % HW;
    t /= HW;
    int f = t % Cout;
    int n = t / Cout;
    float acc = bias ? bias[f] : 0.f;
    const float *wb = w + f * Cin * 25;
    for (int c = 0; c < Cin; ++c) {
      const float *ib = in + (n * Cin + c) * npix;
      const float *wc = wb + c * 25;
#pragma unroll
      for (int ky = 0; ky < 5; ++ky) {
        int yy = y + ky - 2;
        if ((unsigned)yy >= (unsigned)HW) continue;
#pragma unroll
        for (int kx = 0; kx < 5; ++kx) {
          int xx = x + kx - 2;
          if ((unsigned)xx >= (unsigned)HW) continue;
          acc += ib[yy * HW + xx] * wc[ky * 5 + kx];
        }
      }
    }
    out[idx] = do_relu ? fmaxf(acc, 0.f) : acc;
  }
}

__device__ void maxpool2(const float *__restrict__ in, float *__restrict__ out,
                         int C, int H) {
  int Ho = H / 2;
  int N = 4 * C * Ho * Ho;
  for (int idx = blockIdx.x * NTHR + threadIdx.x; idx < N; idx += GSZ) {
    int xo = idx % Ho;
    int t = idx / Ho;
    int yo = t % Ho;
    t /= Ho;
    const float *ib = in + t * H * H + (yo * 2) * H + xo * 2;
    out[idx] = fmaxf(fmaxf(ib[0], ib[1]), fmaxf(ib[H], ib[H + 1]));
  }
}

__device__ void bn_stats(const float *in, int C, int npix, float *red) {
  int cnt = 4 * npix;
  for (int c = blockIdx.x; c < C; c += NBLK) {
    float s = 0.f, ss = 0.f;
    for (int i = threadIdx.x; i < cnt; i += NTHR) {
      int n = i / npix, pp = i % npix;
      float v = in[(n * C + c) * npix + pp];
      s += v;
      ss += v * v;
    }
    s = block_reduce(s, red);
    ss = block_reduce(ss, red);
    if (threadIdx.x == 0) {
      float m = s / (float)cnt;
      float var = fmaxf(ss / (float)cnt - m * m, 0.f);
      g_m[c] = m;
      g_rs[c] = rsqrtf(var + 1e-5f);
    }
    __syncthreads();
  }
}

__device__ void bn_apply(float *buf, int C, int npix, const float *gam, const float *bet) {
  int N = 4 * C * npix;
  for (int i = blockIdx.x * NTHR + threadIdx.x; i < N; i += GSZ) {
    int c = (i / npix) % C;
    buf[i] = (buf[i] - g_m[c]) * g_rs[c] * gam[c] + bet[c];
  }
}

// copy padded code a -> dense [n][F][32][32]
__device__ void unpad(const float *__restrict__ ap, float *__restrict__ dense, int F) {
  int N = 4 * F * 1024;
  for (int i = blockIdx.x * NTHR + threadIdx.x; i < N; i += GSZ) {
    int pix = i & 1023;
    int nf = i >> 10;
    int y = pix >> 5, x = pix & 31;
    dense[i] = ap[nf * 1600 + (y + 4) * 40 + (x + 4)];
  }
}

// ============ LCA2 phaseA (R9 shape + zero-row skip) ============
// X-block2, 2 f-partials, 4 c per thread. group jobs (part2, cg4, Y36, xb18) = 5184
__device__ void lca2_phaseA_g(int n, int rank, const float *__restrict__ ap,
                              float *__restrict__ recon, const float *__restrict__ swA) {
  const int NJOB = 2 * 4 * 36 * 18;
  GCHUNK_LOOP(NJOB, rank) {
    int xb = idx % 18;
    int t = idx / 18;
    int Y = t % 36;
    t /= 36;
    int cg = t & 3;
    int part = t >> 2;
    int X0 = xb * 2;
    ull a0 = 0, a1 = 0, a2 = 0, a3 = 0;
    const float *ab = ap + (n * 32 + part * 16) * 1600 + (Y + 4) * 40 + X0;
    const ulonglong2 *wv = (const ulonglong2 *)(swA + part * 6400) + cg;  // [f][tap][16c]
#pragma unroll 2
    for (int ff = 0; ff < 16; ++ff) {
      const float *af = ab + ff * 1600;
      const ulonglong2 *wf = wv + ff * 100;
#pragma unroll
      for (int ky = 0; ky < 5; ++ky) {
        const float2 *rp = (const float2 *)(af - ky * 40);
        float2 v0 = rp[0], v1 = rp[1], v2 = rp[2];
        unsigned nz = (__float_as_uint(v0.x) | __float_as_uint(v0.y)) |
                      (__float_as_uint(v1.x) | __float_as_uint(v1.y)) |
                      (__float_as_uint(v2.x) | __float_as_uint(v2.y));
        if (nz) {  // exact skip: all-zero a-row contributes nothing
          ull d[6];
          d[0] = dup2(v0.x); d[1] = dup2(v0.y); d[2] = dup2(v1.x);
          d[3] = dup2(v1.y); d[4] = dup2(v2.x); d[5] = dup2(v2.y);
#pragma unroll
          for (int kx = 0; kx < 5; ++kx) {
            ulonglong2 w = wf[(ky * 5 + kx) * 4];
            a0 = ffma2(d[4 - kx], w.x, a0);
            a1 = ffma2(d[4 - kx], w.y, a1);
            a2 = ffma2(d[5 - kx], w.x, a2);
            a3 = ffma2(d[5 - kx], w.y, a3);
          }
        }
      }
    }
    int pixb = Y * 36 + X0;
    float *rb = recon + ((n * 16 + cg * 4) * 1296 + pixb) * 2 + part;
    float c0, c1, c2, c3;
    unpack2(a0, c0, c1);
    unpack2(a1, c2, c3);
    rb[0] = c0; rb[2592] = c1; rb[5184] = c2; rb[7776] = c3;
    unpack2(a2, c0, c1);
    unpack2(a3, c2, c3);
    rb[2] = c0; rb[2594] = c1; rb[5186] = c2; rb[7778] = c3;
  }
}

// ============ LCA2 full loop: phaseB u/drive in registers + zero-row skip ============
__device__ void lca2_loop(int n, int rank, int grp, float *__restrict__ ap,
                          float *__restrict__ recon, const float *__restrict__ drive,
                          const float *__restrict__ swA, const float *__restrict__ swB) {
  const int ck = (8192 + GBLK - 1) / GBLK;  // 222
  int j0 = rank * ck;
  int j1 = (j0 + ck < 8192) ? j0 + ck : 8192;
  int idxB = j0 + (int)threadIdx.x;
  bool hasB = ((int)threadIdx.x < ck) && (idxB < j1);
  int pix = 0, g = 0, y = 0, x = 0, f0 = 0;
  float u0 = 0.f, u1 = 0.f, u2 = 0.f, u3 = 0.f;
  float d0 = 0.f, d1 = 0.f, d2 = 0.f, d3 = 0.f;
  if (hasB) {
    pix = idxB & 1023;
    g = idxB >> 10;
    y = pix >> 5;
    x = pix & 31;
    f0 = g * 4;
    d0 = drive[(n * 32 + f0 + 0) * 1024 + pix];
    d1 = drive[(n * 32 + f0 + 1) * 1024 + pix];
    d2 = drive[(n * 32 + f0 + 2) * 1024 + pix];
    d3 = drive[(n * 32 + f0 + 3) * 1024 + pix];
  }
  const float *rbB = recon + n * 16 * 2592;
  const ulonglong2 *wvB = (const ulonglong2 *)swB + g;  // [c][tap][32f]
  float *apb = ap + (n * 32 + f0) * 1600 + (y + 4) * 40 + (x + 4);

  for (int it = 0; it < 500; ++it) {
    lca2_phaseA_g(n, rank, ap, recon, swA);
    group_sync(grp);
    if (hasB) {
      ull acc01 = 0, acc23 = 0;
#pragma unroll 2
      for (int c = 0; c < 16; ++c) {
        const float *rc = rbB + c * 2592;
        const ulonglong2 *wc = wvB + c * 200;
#pragma unroll
        for (int ky = 0; ky < 5; ++ky) {
          const float2 *rrow = (const float2 *)(rc + ((y + ky) * 36 + x) * 2);
          float2 r0 = rrow[0], r1 = rrow[1], r2 = rrow[2], r3 = rrow[3], r4 = rrow[4];
          unsigned nz = (__float_as_uint(r0.x) | __float_as_uint(r0.y)) |
                        (__float_as_uint(r1.x) | __float_as_uint(r1.y)) |
                        (__float_as_uint(r2.x) | __float_as_uint(r2.y)) |
                        (__float_as_uint(r3.x) | __float_as_uint(r3.y)) |
                        (__float_as_uint(r4.x) | __float_as_uint(r4.y));
          if (nz) {  // exact skip: all-zero recon row contributes nothing
            ull rv;
            ulonglong2 w;
            rv = dup2(r0.x + r0.y);
            w = wc[(ky * 5 + 0) * 8];
            acc01 = ffma2(rv, w.x, acc01);
            acc23 = ffma2(rv, w.y, acc23);
            rv = dup2(r1.x + r1.y);
            w = wc[(ky * 5 + 1) * 8];
            acc01 = ffma2(rv, w.x, acc01);
            acc23 = ffma2(rv, w.y, acc23);
            rv = dup2(r2.x + r2.y);
            w = wc[(ky * 5 + 2) * 8];
            acc01 = ffma2(rv, w.x, acc01);
            acc23 = ffma2(rv, w.y, acc23);
            rv = dup2(r3.x + r3.y);
            w = wc[(ky * 5 + 3) * 8];
            acc01 = ffma2(rv, w.x, acc01);
            acc23 = ffma2(rv, w.y, acc23);
            rv = dup2(r4.x + r4.y);
            w = wc[(ky * 5 + 4) * 8];
            acc01 = ffma2(rv, w.x, acc01);
            acc23 = ffma2(rv, w.y, acc23);
          }
        }
      }
      float i0, i1, i2, i3;
      unpack2(acc01, i0, i1);
      unpack2(acc23, i2, i3);
      float av, un;
      av = fmaxf(u0 - 0.5f, 0.f);
      un = u0 + 0.001f * (d0 - u0 - i0 + av);
      u0 = un;
      apb[0] = fmaxf(un - 0.5f, 0.f);
      av = fmaxf(u1 - 0.5f, 0.f);
      un = u1 + 0.001f * (d1 - u1 - i1 + av);
      u1 = un;
      apb[1600] = fmaxf(un - 0.5f, 0.f);
      av = fmaxf(u2 - 0.5f, 0.f);
      un = u2 + 0.001f * (d2 - u2 - i2 + av);
      u2 = un;
      apb[3200] = fmaxf(un - 0.5f, 0.f);
      av = fmaxf(u3 - 0.5f, 0.f);
      un = u3 + 0.001f * (d3 - u3 - i3 + av);
      u3 = un;
      apb[4800] = fmaxf(un - 0.5f, 0.f);
    }
    group_sync(grp);
  }
}

// ============ LCA1 phaseA (R9 shape + zero-row skip) ============
// 4 f-partials. group jobs (part4, pixE) = 5184
__device__ void lca1_phaseA_g(int n, int rank, const float *__restrict__ ap,
                              float *__restrict__ recon, const float *__restrict__ swA) {
  const int NJOB = 4 * 1296;
  GCHUNK_LOOP(NJOB, rank) {
    int pix = idx % 1296;
    int part = idx / 1296;
    int Y = pix / 36, X = pix % 36;
    int aoff = (Y + 4) * 40 + (X + 4);
    ull acc01 = 0, acc23 = 0;
    const float *ab = ap + (n * 16 + part * 4) * 1600 + aoff;
    const ulonglong2 *wv = (const ulonglong2 *)swA + part * 100;  // [f][tap][4c]
#pragma unroll 2
    for (int ff = 0; ff < 4; ++ff) {
      const float *af = ab + ff * 1600;
      const ulonglong2 *wf = wv + ff * 25;
#pragma unroll
      for (int ky = 0; ky < 5; ++ky) {
        const float *ar = af - ky * 40;
        float av0 = ar[0], av1 = ar[-1], av2 = ar[-2], av3 = ar[-3], av4 = ar[-4];
        unsigned nz = (__float_as_uint(av0) | __float_as_uint(av1)) |
                      (__float_as_uint(av2) | __float_as_uint(av3)) |
                      __float_as_uint(av4);
        if (nz) {
          ulonglong2 w;
          ull av2p;
          av2p = dup2(av0);
          w = wf[ky * 5 + 0];
          acc01 = ffma2(av2p, w.x, acc01);
          acc23 = ffma2(av2p, w.y, acc23);
          av2p = dup2(av1);
          w = wf[ky * 5 + 1];
          acc01 = ffma2(av2p, w.x, acc01);
          acc23 = ffma2(av2p, w.y, acc23);
          av2p = dup2(av2);
          w = wf[ky * 5 + 2];
          acc01 = ffma2(av2p, w.x, acc01);
          acc23 = ffma2(av2p, w.y, acc23);
          av2p = dup2(av3);
          w = wf[ky * 5 + 3];
          acc01 = ffma2(av2p, w.x, acc01);
          acc23 = ffma2(av2p, w.y, acc23);
          av2p = dup2(av4);
          w = wf[ky * 5 + 4];
          acc01 = ffma2(av2p, w.x, acc01);
          acc23 = ffma2(av2p, w.y, acc23);
        }
      }
    }
    float c0, c1, c2, c3;
    unpack2(acc01, c0, c1);
    unpack2(acc23, c2, c3);
    float *rbb = recon + (n * 3 * 1296 + pix) * 4 + part;  // [n][3c][1296][4]
    rbb[0] = c0;
    rbb[5184] = c1;
    rbb[10368] = c2;
  }
}

// ============ LCA1 full loop: phaseB u/drive in registers ============
__device__ void lca1_loop(int n, int rank, int grp, float *__restrict__ ap,
                          float *__restrict__ recon, const float *__restrict__ drive,
                          const float *__restrict__ swA, const float *__restrict__ swB) {
  const int ck = (16384 + GBLK - 1) / GBLK;  // 443
  int j0 = rank * ck;
  int j1 = (j0 + ck < 16384) ? j0 + ck : 16384;
  int idxB = j0 + (int)threadIdx.x;
  bool hasB = ((int)threadIdx.x < ck) && (idxB < j1);
  int pix = 0, f = 0, y = 0, x = 0;
  float u = 0.f, d = 0.f;
  if (hasB) {
    pix = idxB & 1023;
    f = idxB >> 10;
    y = pix >> 5;
    x = pix & 31;
    d = drive[(n * 16 + f) * 1024 + pix];
  }
  const float *rbB = recon + n * 3 * 5184;
  const float *wbB = swB + f;  // [c][tap][16f]
  float *apb = ap + (n * 16 + f) * 1600 + (y + 4) * 40 + (x + 4);

  for (int it = 0; it < 500; ++it) {
    lca1_phaseA_g(n, rank, ap, recon, swA);
    group_sync(grp);
    if (hasB) {
      float acc = 0.f;
#pragma unroll
      for (int c = 0; c < 3; ++c) {
        const float *rc = rbB + c * 5184;
        const float *wc = wbB + c * 400;
#pragma unroll
        for (int ky = 0; ky < 5; ++ky) {
          const float4 *rrow = (const float4 *)(rc + ((y + ky) * 36 + x) * 4);
#pragma unroll
          for (int kx = 0; kx < 5; ++kx) {
            float4 r4 = rrow[kx];
            float rv = (r4.x + r4.z) + (r4.y + r4.w);
            acc += rv * wc[(ky * 5 + kx) * 16];
          }
        }
      }
      float av = fmaxf(u - 0.5f, 0.f);
      float un = u + 0.001f * (d - u - acc + av);
      u = un;
      apb[0] = fmaxf(un - 0.5f, 0.f);
    }
    group_sync(grp);
  }
}

// ---- split-K fully-connected ----
__device__ void fc_partial(const float *__restrict__ in, const float *__restrict__ w,
                           float *__restrict__ part, int K, int J, int KP) {
  int kw = K / KP;
  const int NJOB = 4 * J * KP;
  CHUNK_LOOP(NJOB) {
    int kp = idx % KP;
    int t = idx / KP;
    int j = t % J, n = t / J;
    const float *ir = in + n * K + kp * kw;
    const float *wr = w + j * K + kp * kw;
    float acc = 0.f;
    for (int k = 0; k < kw; ++k) acc += ir[k] * wr[k];
    part[idx] = acc;
  }
}

__device__ void fc_reduce(const float *__restrict__ part, const float *__restrict__ bias,
                          float *__restrict__ out, int J, int KP, bool do_relu) {
  const int NJOB = 4 * J;
  for (int idx = blockIdx.x * NTHR + threadIdx.x; idx < NJOB; idx += GSZ) {
    float acc = bias[idx % J];
    for (int kp = 0; kp < KP; ++kp) acc += part[idx * KP + kp];
    out[idx] = do_relu ? fmaxf(acc, 0.f) : acc;
  }
}

// ===================== the whole network, one persistent kernel =====================
__global__ void __launch_bounds__(NTHR, 1) splitnn_kernel(P p) {
  extern __shared__ float smem[];
  float *swA = smem + SW_A;
  float *swB = smem + SW_B;
  float *red = smem + RED_OFF;

  const int grp = blockIdx.x / GBLK;   // 0..3 (sample id for LCA loops)
  const int rank = blockIdx.x % GBLK;  // 0..36

  // ---- stage LCA1 weights: swA1 [f][tap][4c], swB1 [c][tap][16f] ----
  for (int i = threadIdx.x; i < 1600; i += NTHR) {
    int f = i / 100, r = i % 100, tap = r >> 2, c = r & 3;
    swA[i] = (c < 3) ? p.w1[(f * 3 + c) * 25 + tap] : 0.f;
  }
  for (int i = threadIdx.x; i < 1200; i += NTHR) {
    int c = i / 400, r = i % 400, tap = r >> 4, f = r & 15;
    swB[i] = p.w1[(f * 3 + c) * 25 + tap];
  }

  // ---- standardize input, drive1, a=0 ----
  sample_stats(p.x, 3072, red);
  grid_sync();
  standardize(p.x, g_xs, 3072);
  zero_buf(g_a, 102400);  // padded a for F=16 (incl. zero border)
  grid_sync();
  conv5x5(g_xs, p.w1, nullptr, g_drive, 3, 16, 32, false);
  grid_sync();

  // ---- LCA1: per-sample groups, u/drive register-resident ----
  lca1_loop(grp, rank, grp, g_a, g_recon, g_drive, swA, swB);
  grid_sync();
  unpad(g_a, g_h, 16);
  grid_sync();
  bn_stats(g_h, 16, 1024, red);
  grid_sync();
  bn_apply(g_h, 16, 1024, p.bn1g, p.bn1b);
  grid_sync();

  // ---- stage LCA2 weights, standardize, drive2 ----
  sample_stats(g_h, 16384, red);
  grid_sync();
  standardize(g_h, g_xs, 16384);
  grid_sync();
  conv5x5(g_xs, p.w2, nullptr, g_drive, 16, 32, 32, false);
  zero_buf(g_a, 204800);  // padded a for F=32
  for (int i = threadIdx.x; i < 12800; i += NTHR) {
    int f = i / 400, r = i % 400, tap = r >> 4, c = r & 15;
    swA[i] = p.w2[(f * 16 + c) * 25 + tap];
  }
  for (int i = threadIdx.x; i < 12800; i += NTHR) {
    int c = i / 800, r = i % 800, tap = r >> 5, f = r & 31;
    swB[i] = p.w2[(f * 16 + c) * 25 + tap];
  }
  grid_sync();

  // ---- LCA2: per-sample groups, u/drive register-resident ----
  lca2_loop(grp, rank, grp, g_a, g_recon, g_drive, swA, swB);
  grid_sync();
  unpad(g_a, g_h, 32);
  grid_sync();
  maxpool2(g_h, g_xs, 32, 32);
  grid_sync();
  bn_stats(g_xs, 32, 256, red);
  grid_sync();
  bn_apply(g_xs, 32, 256, p.bn2g, p.bn2b);
  grid_sync();

  // ---- conv tail ----
  conv5x5(g_xs, p.wc1, p.bc1, g_h, 32, 64, 16, true);
  grid_sync();
  maxpool2(g_h, g_drive, 64, 16);
  grid_sync();
  bn_stats(g_drive, 64, 64, red);
  grid_sync();
  bn_apply(g_drive, 64, 64, p.bn3g, p.bn3b);
  grid_sync();
  conv5x5(g_drive, p.wc2, p.bc2, g_h, 64, 128, 8, true);
  grid_sync();
  maxpool2(g_h, g_xs, 128, 8);
  grid_sync();
  bn_stats(g_xs, 128, 16, red);
  grid_sync();
  bn_apply(g_xs, 128, 16, p.bn4g, p.bn4b);
  grid_sync();
  conv5x5(g_xs, p.wc3, p.bc3, g_h, 128, 256, 4, true);
  grid_sync();
  maxpool2(g_h, g_drive, 256, 4);  // [4,256,2,2] == flat [4,1024]
  grid_sync();
  bn_stats(g_drive, 256, 4, red);
  grid_sync();
  bn_apply(g_drive, 256, 4, p.bn5g, p.bn5b);
  grid_sync();

  // ---- classifier (split-K) ----
  fc_partial(g_drive, p.wf1, g_fcp, 1024, 512, 8);
  grid_sync();
  fc_reduce(g_fcp, p.bf1, g_fc, 512, 8, true);
  grid_sync();
  fc_partial(g_fc, p.wf2, g_fcp, 512, 10, 8);
  grid_sync();
  fc_reduce(g_fcp, p.bf2, p.out, 10, 8, false);
}

extern "C" void kernel_launch(void *const *d_in, const int *in_sizes, int n_in,
                              void *d_out, int out_size) {
  (void)in_sizes;
  (void)n_in;
  (void)out_size;
  P p;
  p.x = (const float *)d_in[0];
  p.w1 = (const float *)d_in[1];
  p.w2 = (const float *)d_in[2];
  p.bn1g = (const float *)d_in[3];
  p.bn1b = (const float *)d_in[4];
  p.bn2g = (const float *)d_in[5];
  p.bn2b = (const float *)d_in[6];
  p.wc1 = (const float *)d_in[7];
  p.bc1 = (const float *)d_in[8];
  p.bn3g = (const float *)d_in[9];
  p.bn3b = (const float *)d_in[10];
  p.wc2 = (const float *)d_in[11];
  p.bc2 = (const float *)d_in[12];
  p.bn4g = (const float *)d_in[13];
  p.bn4b = (const float *)d_in[14];
  p.wc3 = (const float *)d_in[15];
  p.bc3 = (const float *)d_in[16];
  p.bn5g = (const float *)d_in[17];
  p.bn5b = (const float *)d_in[18];
  p.wf1 = (const float *)d_in[19];
  p.bf1 = (const float *)d_in[20];
  p.wf2 = (const float *)d_in[21];
  p.bf2 = (const float *)d_in[22];
  p.out = (float *)d_out;

  cudaFuncSetAttribute(reinterpret_cast<const void *>(splitnn_kernel),
                       cudaFuncAttributeMaxDynamicSharedMemorySize, SMEM_BYTES);
  splitnn_kernel<<<NBLK, NTHR, SMEM_BYTES>>>(p);
}

// round 16
// speedup vs baseline: 1.4835x; 1.4835x over previous
#include <cuda_runtime.h>

#define NBLK 148
#define NTHR 512
#define GSZ (NBLK * NTHR)
#define GBLK 37  // blocks per sample group (148 = 4*37)

typedef unsigned long long ull;

// smem layout (floats)
#define SW_A 0         // 12800: phaseA weights
#define SW_B 12800     // 12800: phaseB weights
#define RED_OFF 25600  // 512: reduction scratch
#define SMEM_FLOATS 26112
#define SMEM_BYTES (SMEM_FLOATS * 4)

struct P {
  const float *x, *w1, *w2;
  const float *bn1g, *bn1b, *bn2g, *bn2b;
  const float *wc1, *bc1, *bn3g, *bn3b;
  const float *wc2, *bc2, *bn4g, *bn4b;
  const float *wc3, *bc3, *bn5g, *bn5b;
  const float *wf1, *bf1, *wf2, *bf2;
  float *out;
};

// ---- f32x2 packed helpers (sm_103a FFMA2 path) ----
__device__ __forceinline__ ull dup2(float v) {
  ull r;
  asm("mov.b64 %0, {%1, %1};" : "=l"(r) : "f"(v));
  return r;
}
__device__ __forceinline__ void unpack2(ull p, float &lo, float &hi) {
  asm("mov.b64 {%0, %1}, %2;" : "=f"(lo), "=f"(hi) : "l"(p));
}
__device__ __forceinline__ ull ffma2(ull a, ull b, ull c) {
  ull d;
  asm("fma.rn.f32x2 %0, %1, %2, %3;" : "=l"(d) : "l"(a), "l"(b), "l"(c));
  return d;
}

// ---- persistent-kernel scratch (device globals; no allocation) ----
__device__ unsigned int g_cnt = 0;
__device__ volatile unsigned int g_gen = 0;
__device__ unsigned int g_cnt4[4] = {0, 0, 0, 0};
__device__ volatile unsigned int g_gen4[4] = {0, 0, 0, 0};
__device__ unsigned int g_T1[4];

__device__ float g_xs[131072];
__device__ float g_drive[131072];
__device__ float g_a[204800];      // PADDED code a: [n][F][40][40], zero border
__device__ float g_recon[165888];  // LCA2: [n][16c][1296][2p]; LCA1: [n][3c][1296][4p]
__device__ float g_h[131072];
__device__ float g_m[256];
__device__ float g_rs[256];
__device__ float g_fc[2048];
__device__ float g_fcp[16384];

// chunk over the FULL grid
#define CHUNK_LOOP(NJOB)                                                   \
  const int _ck = ((NJOB) + NBLK - 1) / NBLK;                              \
  const int _j0 = blockIdx.x * _ck;                                        \
  const int _j1 = (_j0 + _ck < (NJOB)) ? (_j0 + _ck) : (NJOB);             \
  for (int idx = _j0 + (int)threadIdx.x; idx < _j1; idx += NTHR)

// chunk over one 37-block group (rank = position within group)
#define GCHUNK_LOOP(NJOB, RANK)                                            \
  const int _ck = ((NJOB) + GBLK - 1) / GBLK;                              \
  const int _j0 = (RANK) * _ck;                                            \
  const int _j1 = (_j0 + _ck < (NJOB)) ? (_j0 + _ck) : (NJOB);             \
  for (int idx = _j0 + (int)threadIdx.x; idx < _j1; idx += NTHR)

// ---- software grid barrier (all 148 blocks) ----
__device__ __forceinline__ void grid_sync() {
  __syncthreads();
  if (threadIdx.x == 0) {
    unsigned int gen = g_gen;
    __threadfence();  // release
    if (atomicAdd(&g_cnt, 1u) == (unsigned)(NBLK - 1)) {
      g_cnt = 0u;
      __threadfence();
      g_gen = gen + 1u;
    } else {
      while (g_gen == gen) {}
      __threadfence();  // acquire (CCTL.IVALL -> drop stale L1)
    }
  }
  __syncthreads();
}

// ---- per-sample group barrier (37 blocks) ----
__device__ __forceinline__ void group_sync(int grp) {
  __syncthreads();
  if (threadIdx.x == 0) {
    unsigned int gen = g_gen4[grp];
    __threadfence();  // release
    if (atomicAdd(&g_cnt4[grp], 1u) == (unsigned)(GBLK - 1)) {
      g_cnt4[grp] = 0u;
      __threadfence();
      g_gen4[grp] = gen + 1u;
    } else {
      while (g_gen4[grp] == gen) {}
      __threadfence();  // acquire
    }
  }
  __syncthreads();
}

__device__ __forceinline__ float block_reduce(float v, float *red) {
  red[threadIdx.x] = v;
  __syncthreads();
#pragma unroll
  for (int s = NTHR / 2; s > 0; s >>= 1) {
    if (threadIdx.x < s) red[threadIdx.x] += red[threadIdx.x + s];
    __syncthreads();
  }
  float r = red[0];
  __syncthreads();
  return r;
}

__device__ void zero_buf(float *b, int n) {
  for (int i = blockIdx.x * NTHR + threadIdx.x; i < n; i += GSZ) b[i] = 0.f;
}

__device__ void sample_stats(const float *in, int len, float *red) {
  for (int n = blockIdx.x; n < 4; n += NBLK) {
    const float *p = in + n * len;
    float s = 0.f, ss = 0.f;
    for (int i = threadIdx.x; i < len; i += NTHR) {
      float v = p[i];
      s += v;
      ss += v * v;
    }
    s = block_reduce(s, red);
    ss = block_reduce(ss, red);
    if (threadIdx.x == 0) {
      float m = s / (float)len;
      float var = fmaxf(ss / (float)len - m * m, 0.f);
      g_m[n] = m;
      g_rs[n] = 1.f / (sqrtf(var) + 1e-8f);
    }
    __syncthreads();
  }
}

__device__ void standardize(const float *in, float *out, int len) {
  for (int i = blockIdx.x * NTHR + threadIdx.x; i < 4 * len; i += GSZ) {
    int n = i / len;
    out[i] = (in[i] - g_m[n]) * g_rs[n];
  }
}

__device__ void conv5x5(const float *__restrict__ in, const float *__restrict__ w,
                        const float *__restrict__ bias, float *__restrict__ out,
                        int Cin, int Cout, int HW, bool do_relu) {
  int npix = HW * HW;
  const int NJOB = 4 * Cout * npix;
  CHUNK_LOOP(NJOB) {
    int x = idx % HW;
    int t = idx / HW;
    int y = t % HW;
    t /= HW;
    int f = t % Cout;
    int n = t / Cout;
    float acc = bias ? bias[f] : 0.f;
    const float *wb = w + f * Cin * 25;
    for (int c = 0; c < Cin; ++c) {
      const float *ib = in + (n * Cin + c) * npix;
      const float *wc = wb + c * 25;
#pragma unroll
      for (int ky = 0; ky < 5; ++ky) {
        int yy = y + ky - 2;
        if ((unsigned)yy >= (unsigned)HW) continue;
#pragma unroll
        for (int kx = 0; kx < 5; ++kx) {
          int xx = x + kx - 2;
          if ((unsigned)xx >= (unsigned)HW) continue;
          acc += ib[yy * HW + xx] * wc[ky * 5 + kx];
        }
      }
    }
    out[idx] = do_relu ? fmaxf(acc, 0.f) : acc;
  }
}

__device__ void maxpool2(const float *__restrict__ in, float *__restrict__ out,
                         int C, int H) {
  int Ho = H / 2;
  int N = 4 * C * Ho * Ho;
  for (int idx = blockIdx.x * NTHR + threadIdx.x; idx < N; idx += GSZ) {
    int xo = idx % Ho;
    int t = idx / Ho;
    int yo = t % Ho;
    t /= Ho;
    const float *ib = in + t * H * H + (yo * 2) * H + xo * 2;
    out[idx] = fmaxf(fmaxf(ib[0], ib[1]), fmaxf(ib[H], ib[H + 1]));
  }
}

__device__ void bn_stats(const float *in, int C, int npix, float *red) {
  int cnt = 4 * npix;
  for (int c = blockIdx.x; c < C; c += NBLK) {
    float s = 0.f, ss = 0.f;
    for (int i = threadIdx.x; i < cnt; i += NTHR) {
      int n = i / npix, pp = i % npix;
      float v = in[(n * C + c) * npix + pp];
      s += v;
      ss += v * v;
    }
    s = block_reduce(s, red);
    ss = block_reduce(ss, red);
    if (threadIdx.x == 0) {
      float m = s / (float)cnt;
      float var = fmaxf(ss / (float)cnt - m * m, 0.f);
      g_m[c] = m;
      g_rs[c] = rsqrtf(var + 1e-5f);
    }
    __syncthreads();
  }
}

__device__ void bn_apply(float *buf, int C, int npix, const float *gam, const float *bet) {
  int N = 4 * C * npix;
  for (int i = blockIdx.x * NTHR + threadIdx.x; i < N; i += GSZ) {
    int c = (i / npix) % C;
    buf[i] = (buf[i] - g_m[c]) * g_rs[c] * gam[c] + bet[c];
  }
}

// copy padded code a -> dense [n][F][32][32]
__device__ void unpad(const float *__restrict__ ap, float *__restrict__ dense, int F) {
  int N = 4 * F * 1024;
  for (int i = blockIdx.x * NTHR + threadIdx.x; i < N; i += GSZ) {
    int pix = i & 1023;
    int nf = i >> 10;
    int y = pix >> 5, x = pix & 31;
    dense[i] = ap[nf * 1600 + (y + 4) * 40 + (x + 4)];
  }
}

// ============ LCA2 phaseA (R9 shape) ============
__device__ void lca2_phaseA_g(int n, int rank, const float *__restrict__ ap,
                              float *__restrict__ recon, const float *__restrict__ swA) {
  const int NJOB = 2 * 4 * 36 * 18;
  GCHUNK_LOOP(NJOB, rank) {
    int xb = idx % 18;
    int t = idx / 18;
    int Y = t % 36;
    t /= 36;
    int cg = t & 3;
    int part = t >> 2;
    int X0 = xb * 2;
    ull a0 = 0, a1 = 0, a2 = 0, a3 = 0;
    const float *ab = ap + (n * 32 + part * 16) * 1600 + (Y + 4) * 40 + X0;
    const ulonglong2 *wv = (const ulonglong2 *)(swA + part * 6400) + cg;  // [f][tap][16c]
#pragma unroll 2
    for (int ff = 0; ff < 16; ++ff) {
      const float *af = ab + ff * 1600;
      const ulonglong2 *wf = wv + ff * 100;
#pragma unroll
      for (int ky = 0; ky < 5; ++ky) {
        const float2 *rp = (const float2 *)(af - ky * 40);
        float2 v0 = rp[0], v1 = rp[1], v2 = rp[2];
        ull d[6];
        d[0] = dup2(v0.x); d[1] = dup2(v0.y); d[2] = dup2(v1.x);
        d[3] = dup2(v1.y); d[4] = dup2(v2.x); d[5] = dup2(v2.y);
#pragma unroll
        for (int kx = 0; kx < 5; ++kx) {
          ulonglong2 w = wf[(ky * 5 + kx) * 4];
          a0 = ffma2(d[4 - kx], w.x, a0);
          a1 = ffma2(d[4 - kx], w.y, a1);
          a2 = ffma2(d[5 - kx], w.x, a2);
          a3 = ffma2(d[5 - kx], w.y, a3);
        }
      }
    }
    int pixb = Y * 36 + X0;
    float *rb = recon + ((n * 16 + cg * 4) * 1296 + pixb) * 2 + part;
    float c0, c1, c2, c3;
    unpack2(a0, c0, c1);
    unpack2(a1, c2, c3);
    rb[0] = c0; rb[2592] = c1; rb[5184] = c2; rb[7776] = c3;
    unpack2(a2, c0, c1);
    unpack2(a3, c2, c3);
    rb[2] = c0; rb[2594] = c1; rb[5186] = c2; rb[7778] = c3;
  }
}

// ============ LCA2 full loop: u/drive in registers + exact fast-forward ============
__device__ void lca2_loop(int n, int rank, int grp, float *__restrict__ ap,
                          float *__restrict__ recon, const float *__restrict__ drive,
                          const float *__restrict__ swA, const float *__restrict__ swB) {
  const int ck = (8192 + GBLK - 1) / GBLK;  // 222
  int j0 = rank * ck;
  int j1 = (j0 + ck < 8192) ? j0 + ck : 8192;
  int idxB = j0 + (int)threadIdx.x;
  bool hasB = ((int)threadIdx.x < ck) && (idxB < j1);
  int pix = 0, g = 0, y = 0, x = 0, f0 = 0;
  float u0 = 0.f, u1 = 0.f, u2 = 0.f, u3 = 0.f;
  float d0 = 0.f, d1 = 0.f, d2 = 0.f, d3 = 0.f;
  if (hasB) {
    pix = idxB & 1023;
    g = idxB >> 10;
    y = pix >> 5;
    x = pix & 31;
    f0 = g * 4;
    d0 = drive[(n * 32 + f0 + 0) * 1024 + pix];
    d1 = drive[(n * 32 + f0 + 1) * 1024 + pix];
    d2 = drive[(n * 32 + f0 + 2) * 1024 + pix];
    d3 = drive[(n * 32 + f0 + 3) * 1024 + pix];
  }
  const float *rbB = recon + n * 16 * 2592;
  const ulonglong2 *wvB = (const ulonglong2 *)swB + g;  // [c][tap][32f]
  float *apb = ap + (n * 32 + f0) * 1600 + (y + 4) * 40 + (x + 4);

  // ---- crossing-time simulation (inhib-free; bit-identical update expr) ----
  if (hasB) {
    float s0 = 0.f, s1 = 0.f, s2 = 0.f, s3 = 0.f;
    unsigned c = 500u;
    for (int t = 0; t < 500; ++t) {
      float i0 = 0.0f, av;
      av = fmaxf(s0 - 0.5f, 0.f); s0 = s0 + 0.001f * (d0 - s0 - i0 + av);
      av = fmaxf(s1 - 0.5f, 0.f); s1 = s1 + 0.001f * (d1 - s1 - i0 + av);
      av = fmaxf(s2 - 0.5f, 0.f); s2 = s2 + 0.001f * (d2 - s2 - i0 + av);
      av = fmaxf(s3 - 0.5f, 0.f); s3 = s3 + 0.001f * (d3 - s3 - i0 + av);
      float mx = fmaxf(fmaxf(s0, s1), fmaxf(s2, s3));
      if (mx > 0.5f) { c = (unsigned)(t + 1); break; }
    }
    atomicMin(&g_T1[grp], c);
  }
  group_sync(grp);
  int T = (int)__ldcg(&g_T1[grp]);
  // ---- fast-forward T updates in registers; materialize a(u_T) ----
  if (hasB) {
    for (int t = 0; t < T; ++t) {
      float i0 = 0.0f, av;
      av = fmaxf(u0 - 0.5f, 0.f); u0 = u0 + 0.001f * (d0 - u0 - i0 + av);
      av = fmaxf(u1 - 0.5f, 0.f); u1 = u1 + 0.001f * (d1 - u1 - i0 + av);
      av = fmaxf(u2 - 0.5f, 0.f); u2 = u2 + 0.001f * (d2 - u2 - i0 + av);
      av = fmaxf(u3 - 0.5f, 0.f); u3 = u3 + 0.001f * (d3 - u3 - i0 + av);
    }
    apb[0] = fmaxf(u0 - 0.5f, 0.f);
    apb[1600] = fmaxf(u1 - 0.5f, 0.f);
    apb[3200] = fmaxf(u2 - 0.5f, 0.f);
    apb[4800] = fmaxf(u3 - 0.5f, 0.f);
  }
  group_sync(grp);

  for (int it = T; it < 500; ++it) {
    lca2_phaseA_g(n, rank, ap, recon, swA);
    group_sync(grp);
    if (hasB) {
      ull acc01 = 0, acc23 = 0;
#pragma unroll 2
      for (int c = 0; c < 16; ++c) {
        const float *rc = rbB + c * 2592;
        const ulonglong2 *wc = wvB + c * 200;
#pragma unroll
        for (int ky = 0; ky < 5; ++ky) {
          const float2 *rrow = (const float2 *)(rc + ((y + ky) * 36 + x) * 2);
#pragma unroll
          for (int kx = 0; kx < 5; ++kx) {
            float2 r2 = rrow[kx];
            ull rv2 = dup2(r2.x + r2.y);
            ulonglong2 w = wc[(ky * 5 + kx) * 8];
            acc01 = ffma2(rv2, w.x, acc01);
            acc23 = ffma2(rv2, w.y, acc23);
          }
        }
      }
      float i0, i1, i2, i3;
      unpack2(acc01, i0, i1);
      unpack2(acc23, i2, i3);
      float av, un;
      av = fmaxf(u0 - 0.5f, 0.f);
      un = u0 + 0.001f * (d0 - u0 - i0 + av);
      u0 = un;
      apb[0] = fmaxf(un - 0.5f, 0.f);
      av = fmaxf(u1 - 0.5f, 0.f);
      un = u1 + 0.001f * (d1 - u1 - i1 + av);
      u1 = un;
      apb[1600] = fmaxf(un - 0.5f, 0.f);
      av = fmaxf(u2 - 0.5f, 0.f);
      un = u2 + 0.001f * (d2 - u2 - i2 + av);
      u2 = un;
      apb[3200] = fmaxf(un - 0.5f, 0.f);
      av = fmaxf(u3 - 0.5f, 0.f);
      un = u3 + 0.001f * (d3 - u3 - i3 + av);
      u3 = un;
      apb[4800] = fmaxf(un - 0.5f, 0.f);
    }
    group_sync(grp);
  }
}

// ============ LCA1 phaseA (R9 shape) ============
__device__ void lca1_phaseA_g(int n, int rank, const float *__restrict__ ap,
                              float *__restrict__ recon, const float *__restrict__ swA) {
  const int NJOB = 4 * 1296;
  GCHUNK_LOOP(NJOB, rank) {
    int pix = idx % 1296;
    int part = idx / 1296;
    int Y = pix / 36, X = pix % 36;
    int aoff = (Y + 4) * 40 + (X + 4);
    ull acc01 = 0, acc23 = 0;
    const float *ab = ap + (n * 16 + part * 4) * 1600 + aoff;
    const ulonglong2 *wv = (const ulonglong2 *)swA + part * 100;  // [f][tap][4c]
#pragma unroll 2
    for (int ff = 0; ff < 4; ++ff) {
      const float *af = ab + ff * 1600;
      const ulonglong2 *wf = wv + ff * 25;
#pragma unroll
      for (int ky = 0; ky < 5; ++ky) {
#pragma unroll
        for (int kx = 0; kx < 5; ++kx) {
          float av = af[-(ky * 40 + kx)];
          ull av2 = dup2(av);
          ulonglong2 w = wf[ky * 5 + kx];
          acc01 = ffma2(av2, w.x, acc01);
          acc23 = ffma2(av2, w.y, acc23);
        }
      }
    }
    float c0, c1, c2, c3;
    unpack2(acc01, c0, c1);
    unpack2(acc23, c2, c3);
    float *rbb = recon + (n * 3 * 1296 + pix) * 4 + part;  // [n][3c][1296][4]
    rbb[0] = c0;
    rbb[5184] = c1;
    rbb[10368] = c2;
  }
}

// ============ LCA1 full loop: u/drive in registers + exact fast-forward ============
__device__ void lca1_loop(int n, int rank, int grp, float *__restrict__ ap,
                          float *__restrict__ recon, const float *__restrict__ drive,
                          const float *__restrict__ swA, const float *__restrict__ swB) {
  const int ck = (16384 + GBLK - 1) / GBLK;  // 443
  int j0 = rank * ck;
  int j1 = (j0 + ck < 16384) ? j0 + ck : 16384;
  int idxB = j0 + (int)threadIdx.x;
  bool hasB = ((int)threadIdx.x < ck) && (idxB < j1);
  int pix = 0, f = 0, y = 0, x = 0;
  float u = 0.f, d = 0.f;
  if (hasB) {
    pix = idxB & 1023;
    f = idxB >> 10;
    y = pix >> 5;
    x = pix & 31;
    d = drive[(n * 16 + f) * 1024 + pix];
  }
  const float *rbB = recon + n * 3 * 5184;
  const float *wbB = swB + f;  // [c][tap][16f]
  float *apb = ap + (n * 16 + f) * 1600 + (y + 4) * 40 + (x + 4);

  // ---- crossing-time simulation ----
  if (hasB) {
    float s = 0.f;
    unsigned c = 500u;
    for (int t = 0; t < 500; ++t) {
      float i0 = 0.0f;
      float av = fmaxf(s - 0.5f, 0.f);
      s = s + 0.001f * (d - s - i0 + av);
      if (s > 0.5f) { c = (unsigned)(t + 1); break; }
    }
    atomicMin(&g_T1[grp], c);
  }
  group_sync(grp);
  int T = (int)__ldcg(&g_T1[grp]);
  if (hasB) {
    for (int t = 0; t < T; ++t) {
      float i0 = 0.0f;
      float av = fmaxf(u - 0.5f, 0.f);
      u = u + 0.001f * (d - u - i0 + av);
    }
    apb[0] = fmaxf(u - 0.5f, 0.f);
  }
  group_sync(grp);

  for (int it = T; it < 500; ++it) {
    lca1_phaseA_g(n, rank, ap, recon, swA);
    group_sync(grp);
    if (hasB) {
      float acc = 0.f;
#pragma unroll
      for (int c = 0; c < 3; ++c) {
        const float *rc = rbB + c * 5184;
        const float *wc = wbB + c * 400;
#pragma unroll
        for (int ky = 0; ky < 5; ++ky) {
          const float4 *rrow = (const float4 *)(rc + ((y + ky) * 36 + x) * 4);
#pragma unroll
          for (int kx = 0; kx < 5; ++kx) {
            float4 r4 = rrow[kx];
            float rv = (r4.x + r4.z) + (r4.y + r4.w);
            acc += rv * wc[(ky * 5 + kx) * 16];
          }
        }
      }
      float av = fmaxf(u - 0.5f, 0.f);
      float un = u + 0.001f * (d - u - acc + av);
      u = un;
      apb[0] = fmaxf(un - 0.5f, 0.f);
    }
    group_sync(grp);
  }
}

// ---- split-K fully-connected ----
__device__ void fc_partial(const float *__restrict__ in, const float *__restrict__ w,
                           float *__restrict__ part, int K, int J, int KP) {
  int kw = K / KP;
  const int NJOB = 4 * J * KP;
  CHUNK_LOOP(NJOB) {
    int kp = idx % KP;
    int t = idx / KP;
    int j = t % J, n = t / J;
    const float *ir = in + n * K + kp * kw;
    const float *wr = w + j * K + kp * kw;
    float acc = 0.f;
    for (int k = 0; k < kw; ++k) acc += ir[k] * wr[k];
    part[idx] = acc;
  }
}

__device__ void fc_reduce(const float *__restrict__ part, const float *__restrict__ bias,
                          float *__restrict__ out, int J, int KP, bool do_relu) {
  const int NJOB = 4 * J;
  for (int idx = blockIdx.x * NTHR + threadIdx.x; idx < NJOB; idx += GSZ) {
    float acc = bias[idx % J];
    for (int kp = 0; kp < KP; ++kp) acc += part[idx * KP + kp];
    out[idx] = do_relu ? fmaxf(acc, 0.f) : acc;
  }
}

// ===================== the whole network, one persistent kernel =====================
__global__ void __launch_bounds__(NTHR, 1) splitnn_kernel(P p) {
  extern __shared__ float smem[];
  float *swA = smem + SW_A;
  float *swB = smem + SW_B;
  float *red = smem + RED_OFF;

  const int grp = blockIdx.x / GBLK;   // 0..3 (sample id for LCA loops)
  const int rank = blockIdx.x % GBLK;  // 0..36

  // ---- stage LCA1 weights: swA1 [f][tap][4c], swB1 [c][tap][16f] ----
  for (int i = threadIdx.x; i < 1600; i += NTHR) {
    int f = i / 100, r = i % 100, tap = r >> 2, c = r & 3;
    swA[i] = (c < 3) ? p.w1[(f * 3 + c) * 25 + tap] : 0.f;
  }
  for (int i = threadIdx.x; i < 1200; i += NTHR) {
    int c = i / 400, r = i % 400, tap = r >> 4, f = r & 15;
    swB[i] = p.w1[(f * 3 + c) * 25 + tap];
  }
  if (blockIdx.x == 0 && threadIdx.x < 4) g_T1[threadIdx.x] = 500u;

  // ---- standardize input, drive1, a=0 ----
  sample_stats(p.x, 3072, red);
  grid_sync();
  standardize(p.x, g_xs, 3072);
  zero_buf(g_a, 102400);  // padded a for F=16 (incl. zero border)
  grid_sync();
  conv5x5(g_xs, p.w1, nullptr, g_drive, 3, 16, 32, false);
  grid_sync();

  // ---- LCA1 ----
  lca1_loop(grp, rank, grp, g_a, g_recon, g_drive, swA, swB);
  grid_sync();
  unpad(g_a, g_h, 16);
  grid_sync();
  bn_stats(g_h, 16, 1024, red);
  grid_sync();
  bn_apply(g_h, 16, 1024, p.bn1g, p.bn1b);
  grid_sync();

  // ---- stage LCA2 weights, standardize, drive2 ----
  sample_stats(g_h, 16384, red);
  grid_sync();
  standardize(g_h, g_xs, 16384);
  grid_sync();
  conv5x5(g_xs, p.w2, nullptr, g_drive, 16, 32, 32, false);
  zero_buf(g_a, 204800);  // padded a for F=32
  for (int i = threadIdx.x; i < 12800; i += NTHR) {
    int f = i / 400, r = i % 400, tap = r >> 4, c = r & 15;
    swA[i] = p.w2[(f * 16 + c) * 25 + tap];
  }
  for (int i = threadIdx.x; i < 12800; i += NTHR) {
    int c = i / 800, r = i % 800, tap = r >> 5, f = r & 31;
    swB[i] = p.w2[(f * 16 + c) * 25 + tap];
  }
  if (blockIdx.x == 0 && threadIdx.x < 4) g_T1[threadIdx.x] = 500u;
  grid_sync();

  // ---- LCA2 ----
  lca2_loop(grp, rank, grp, g_a, g_recon, g_drive, swA, swB);
  grid_sync();
  unpad(g_a, g_h, 32);
  grid_sync();
  maxpool2(g_h, g_xs, 32, 32);
  grid_sync();
  bn_stats(g_xs, 32, 256, red);
  grid_sync();
  bn_apply(g_xs, 32, 256, p.bn2g, p.bn2b);
  grid_sync();

  // ---- conv tail ----
  conv5x5(g_xs, p.wc1, p.bc1, g_h, 32, 64, 16, true);
  grid_sync();
  maxpool2(g_h, g_drive, 64, 16);
  grid_sync();
  bn_stats(g_drive, 64, 64, red);
  grid_sync();
  bn_apply(g_drive, 64, 64, p.bn3g, p.bn3b);
  grid_sync();
  conv5x5(g_drive, p.wc2, p.bc2, g_h, 64, 128, 8, true);
  grid_sync();
  maxpool2(g_h, g_xs, 128, 8);
  grid_sync();
  bn_stats(g_xs, 128, 16, red);
  grid_sync();
  bn_apply(g_xs, 128, 16, p.bn4g, p.bn4b);
  grid_sync();
  conv5x5(g_xs, p.wc3, p.bc3, g_h, 128, 256, 4, true);
  grid_sync();
  maxpool2(g_h, g_drive, 256, 4);  // [4,256,2,2] == flat [4,1024]
  grid_sync();
  bn_stats(g_drive, 256, 4, red);
  grid_sync();
  bn_apply(g_drive, 256, 4, p.bn5g, p.bn5b);
  grid_sync();

  // ---- classifier (split-K) ----
  fc_partial(g_drive, p.wf1, g_fcp, 1024, 512, 8);
  grid_sync();
  fc_reduce(g_fcp, p.bf1, g_fc, 512, 8, true);
  grid_sync();
  fc_partial(g_fc, p.wf2, g_fcp, 512, 10, 8);
  grid_sync();
  fc_reduce(g_fcp, p.bf2, p.out, 10, 8, false);
}

extern "C" void kernel_launch(void *const *d_in, const int *in_sizes, int n_in,
                              void *d_out, int out_size) {
  (void)in_sizes;
  (void)n_in;
  (void)out_size;
  P p;
  p.x = (const float *)d_in[0];
  p.w1 = (const float *)d_in[1];
  p.w2 = (const float *)d_in[2];
  p.bn1g = (const float *)d_in[3];
  p.bn1b = (const float *)d_in[4];
  p.bn2g = (const float *)d_in[5];
  p.bn2b = (const float *)d_in[6];
  p.wc1 = (const float *)d_in[7];
  p.bc1 = (const float *)d_in[8];
  p.bn3g = (const float *)d_in[9];
  p.bn3b = (const float *)d_in[10];
  p.wc2 = (const float *)d_in[11];
  p.bc2 = (const float *)d_in[12];
  p.bn4g = (const float *)d_in[13];
  p.bn4b = (const float *)d_in[14];
  p.wc3 = (const float *)d_in[15];
  p.bc3 = (const float *)d_in[16];
  p.bn5g = (const float *)d_in[17];
  p.bn5b = (const float *)d_in[18];
  p.wf1 = (const float *)d_in[19];
  p.bf1 = (const float *)d_in[20];
  p.wf2 = (const float *)d_in[21];
  p.bf2 = (const float *)d_in[22];
  p.out = (float *)d_out;

  cudaFuncSetAttribute(reinterpret_cast<const void *>(splitnn_kernel),
                       cudaFuncAttributeMaxDynamicSharedMemorySize, SMEM_BYTES);
  splitnn_kernel<<<NBLK, NTHR, SMEM_BYTES>>>(p);
}